// round 14
// baseline (speedup 1.0000x reference)
#include <cuda_runtime.h>
#include <cuda_bf16.h>

// Problem constants (fixed shapes)
constexpr int QN = 16;      // query rows
constexpr int D  = 384;     // embedding dim
constexpr int NV = D / 4;   // float4 per row
constexpr int N  = 50000;   // corpus docs
constexpr int TOTAL = QN * N;
constexpr int BINBITS = 13;              // sign+8exp+4mant
constexpr int NBIN = 1 << BINBITS;       // 8192 buckets per row

// GEMM tiling
constexpr int TILE = 128;            // docs per block (1 per thread)
constexpr int KC   = 32;             // k-chunk (floats)
constexpr int NCH  = D / KC;         // 12 chunks
constexpr int NTB  = (N + TILE - 1) / TILE;   // 391 blocks

constexpr int PBT = 1024;            // threads in pav_bucket block
constexpr int BPT = NBIN / PBT;      // 8 bins per thread
constexpr int NMRG = 32;             // level-1 mergers
constexpr int LPM  = PBT / NMRG;     // 32 thread-lists per merger
constexpr int MCAP = LPM * BPT;      // 256 bucket cap per merger list

constexpr float FXS_F = 4398046511104.0f;  // 2^42 (pow2 -> exact fp32 scale)
constexpr double FXS = 4398046511104.0;

// ---------------- static device scratch (no allocations allowed) ------------
__device__ float              g_qn[QN * D];       // normalized queries
__device__ unsigned           g_cnt[QN * NBIN];   // bucket counts
__device__ unsigned long long g_zsum[QN * NBIN];  // bucket sum(z), fixed-point
__device__ float              g_bmeanf[QN * NBIN];// bucket -> its block mean

__device__ double g_asum[QN * PBT * BPT];  // phase-A per-thread lists
__device__ int    g_acnt[QN * PBT * BPT];
__device__ int    g_anb[QN * PBT];

__device__ double g_m1s[QN * NMRG * MCAP]; // level-1 merged lists
__device__ int    g_m1c[QN * NMRG * MCAP];
__device__ int    g_m1n[QN * NMRG];

__device__ double g_fs[QN * NBIN];         // final block means
__device__ int    g_fc[QN * NBIN];
__device__ int    g_fe[QN * NBIN];         // final block ends
__device__ int    g_B[QN];                 // final block counts

__device__ __forceinline__ unsigned ord_of(unsigned u) {
    return u ^ ((u & 0x80000000u) ? 0xFFFFFFFFu : 0x80000000u);
}

__device__ __forceinline__ void cp16(void* dst_smem, const void* src) {
    unsigned s = (unsigned)__cvta_generic_to_shared(dst_smem);
    asm volatile("cp.async.cg.shared.global [%0], [%1], 16;" :: "r"(s), "l"(src));
}

__device__ __forceinline__ unsigned long long fma2(
    unsigned long long a, unsigned long long b, unsigned long long c) {
    unsigned long long d;
    asm("fma.rn.f32x2 %0, %1, %2, %3;" : "=l"(d) : "l"(a), "l"(b), "l"(c));
    return d;
}
__device__ __forceinline__ float sum2(unsigned long long v) {
    return __uint_as_float((unsigned)(v & 0xFFFFFFFFull)) +
           __uint_as_float((unsigned)(v >> 32));
}

// ---------------- prep: zero histograms + normalize q ------------------------
__global__ __launch_bounds__(512) void prep_kernel(const float* __restrict__ qg)
{
    const int gid = blockIdx.x * 512 + threadIdx.x;
    if (gid < QN * NBIN) {
        g_cnt[gid] = 0u;
        g_zsum[gid] = 0ull;
    }
    if (blockIdx.x == 0) {
        const int w = threadIdx.x >> 5, lane = threadIdx.x & 31;  // warp = row
        const float4* src = reinterpret_cast<const float4*>(qg) + w * NV;
        float4 v[3];
        float ss = 0.f;
        #pragma unroll
        for (int j = 0; j < 3; j++) {
            v[j] = src[lane + 32 * j];
            ss += v[j].x*v[j].x + v[j].y*v[j].y + v[j].z*v[j].z + v[j].w*v[j].w;
        }
        #pragma unroll
        for (int o = 16; o; o >>= 1)
            ss += __shfl_xor_sync(0xFFFFFFFFu, ss, o);
        float s = 1.0f / fmaxf(sqrtf(ss), 1e-12f);
        float4* dst = reinterpret_cast<float4*>(g_qn) + w * NV;
        #pragma unroll
        for (int j = 0; j < 3; j++) {
            float4 o4 = v[j];
            o4.x *= s; o4.y *= s; o4.z *= s; o4.w *= s;
            dst[lane + 32 * j] = o4;
        }
    }
}

// ---------------- sims GEMM: f32x2 FFMA2, cp.async double-buffered -----------
// Writes sims row-major directly (coalesced across tid for each r).
__global__ __launch_bounds__(TILE) void sim_tile_kernel(
    const float* __restrict__ cg, float* __restrict__ sims,
    unsigned* __restrict__ cnt, unsigned long long* __restrict__ zsum)
{
    __shared__ ulonglong2 qsh[QN * NV];    // 24 KB normalized q, [r][k/4]
    __shared__ ulonglong2 sc[2][TILE * 8]; // 2 x 16 KB c chunks, XOR-swizzled
    const int tid = threadIdx.x;
    const int d0 = blockIdx.x * TILE;
    const int doc = d0 + tid;
    const bool valid = doc < N;
    const float4* cg4 = reinterpret_cast<const float4*>(cg);

    auto stage = [&](int ch, int buf) {
        const int k4 = ch * (KC / 4);
        #pragma unroll
        for (int i = 0; i < 8; i++) {
            int idx = tid + i * TILE;
            int dd = idx >> 3, f4 = idx & 7;
            int gdoc = min(d0 + dd, N - 1);
            cp16(&sc[buf][dd * 8 + (f4 ^ (dd & 7))],
                 &cg4[(size_t)gdoc * NV + k4 + f4]);
        }
        asm volatile("cp.async.commit_group;" ::: "memory");
    };

    stage(0, 0);
    stage(1, 1);

    {   // stage q while c chunks are in flight
        const ulonglong2* qn4 = reinterpret_cast<const ulonglong2*>(g_qn);
        #pragma unroll
        for (int i = 0; i < (QN * NV) / TILE; i++)
            qsh[tid + i * TILE] = qn4[tid + i * TILE];
    }

    unsigned long long acc[QN];
    #pragma unroll
    for (int r = 0; r < QN; r++) acc[r] = 0ull;
    unsigned long long ssa = 0ull, ssb = 0ull;

    const int sw = (tid & 7);   // xor swizzle key for this thread's row
    for (int ch = 0; ch < NCH; ch++) {
        if (ch < NCH - 1) asm volatile("cp.async.wait_group 1;" ::: "memory");
        else              asm volatile("cp.async.wait_group 0;" ::: "memory");
        __syncthreads();

        const ulonglong2* crow = &sc[ch & 1][tid * 8];
        const int k4 = ch * (KC / 4);
        #pragma unroll
        for (int f4 = 0; f4 < 8; f4++) {
            ulonglong2 cv = crow[f4 ^ sw];
            ssa = fma2(cv.x, cv.x, ssa);
            ssb = fma2(cv.y, cv.y, ssb);
            #pragma unroll
            for (int r = 0; r < QN; r++) {
                ulonglong2 qv = qsh[r * NV + k4 + f4];  // warp-uniform broadcast
                acc[r] = fma2(qv.x, cv.x, acc[r]);
                acc[r] = fma2(qv.y, cv.y, acc[r]);
            }
        }
        __syncthreads();
        if (ch + 2 < NCH) stage(ch + 2, ch & 1);
    }

    if (valid) {
        float ss = sum2(ssa) + sum2(ssb);
        float cinv = 1.0f / fmaxf(sqrtf(ss), 1e-12f);
        #pragma unroll
        for (int r = 0; r < QN; r++) {
            float sim = sum2(acc[r]) * cinv;
            sims[r * N + doc] = sim;                  // coalesced across tid
            unsigned u = __float_as_uint(sim);
            unsigned bin = ((unsigned)r << BINBITS) | (ord_of(u) >> (32 - BINBITS));
            atomicAdd(&cnt[bin], 1u);
            float z = sim * -10.0f;
            long long q = __float2ll_rn(z * FXS_F);   // exact pow2 scale
            atomicAdd(&zsum[bin], (unsigned long long)q);
        }
    }
}

// ---------------- fused bucket PAV + bucket->mean map ------------------------
// One block per row, 1024 threads, 8 contiguous bins each. Bucket at start
// position p with count c pools into (sum = Sz - c*N + c*p + c*(c-1)/2, c).
__global__ __launch_bounds__(PBT) void pav_bucket_kernel(
    const unsigned* __restrict__ cnt, const unsigned long long* __restrict__ zsum,
    float* __restrict__ bmean)
{
    const int row = blockIdx.x;
    const int t = threadIdx.x;
    const int b0 = row * NBIN + t * BPT;

    unsigned lcnt[BPT];
    {
        const uint4* p4 = reinterpret_cast<const uint4*>(cnt + b0);
        #pragma unroll
        for (int j = 0; j < BPT / 4; j++) {
            uint4 v = p4[j];
            lcnt[j*4+0] = v.x; lcnt[j*4+1] = v.y;
            lcnt[j*4+2] = v.z; lcnt[j*4+3] = v.w;
        }
    }
    unsigned tsum = 0;
    #pragma unroll
    for (int j = 0; j < BPT; j++) tsum += lcnt[j];

    __shared__ unsigned s[PBT];
    s[t] = tsum;
    __syncthreads();
    #pragma unroll
    for (int off = 1; off < PBT; off <<= 1) {
        unsigned v = (t >= off) ? s[t - off] : 0u;
        __syncthreads();
        s[t] += v;
        __syncthreads();
    }
    unsigned texcl = s[t] - tsum;

    unsigned lpre[BPT];
    double ls[BPT];
    int    lc[BPT];
    int nb = 0;
    {
        unsigned p = texcl;
        #pragma unroll
        for (int j = 0; j < BPT; j++) {
            lpre[j] = p;
            unsigned c = lcnt[j];
            if (c) {
                double zs = (double)(long long)zsum[b0 + j] * (1.0 / FXS);
                double dc = (double)c;
                double cs = zs - dc * (double)N + dc * (double)p
                            + 0.5 * dc * (double)(c - 1);
                int cc = (int)c;
                while (nb > 0 && ls[nb - 1] * (double)cc < cs * (double)lc[nb - 1]) {
                    cs += ls[nb - 1]; cc += lc[nb - 1]; nb--;
                }
                ls[nb] = cs; lc[nb] = cc; nb++;
            }
            p += c;
        }
    }
    const int ob = (row * PBT + t) * BPT;
    #pragma unroll
    for (int b = 0; b < BPT; b++) {
        if (b < nb) { g_asum[ob + b] = ls[b]; g_acnt[ob + b] = lc[b]; }
    }
    g_anb[row * PBT + t] = nb;
    __syncthreads();

    if (t < NMRG) {
        const int mb = (row * NMRG + t) * MCAP;
        int B = 0;
        for (int tt = t * LPM; tt < t * LPM + LPM; tt++) {
            int nbt = g_anb[row * PBT + tt];
            const int bb = (row * PBT + tt) * BPT;
            for (int b = 0; b < nbt; b++) {
                double cs = g_asum[bb + b];
                int cc = g_acnt[bb + b];
                while (B > 0 && g_m1s[mb + B - 1] * (double)cc < cs * (double)g_m1c[mb + B - 1]) {
                    cs += g_m1s[mb + B - 1]; cc += g_m1c[mb + B - 1]; B--;
                }
                g_m1s[mb + B] = cs; g_m1c[mb + B] = cc; B++;
            }
        }
        g_m1n[row * NMRG + t] = B;
    }
    __syncthreads();

    if (t == 0) {
        const int fb = row * NBIN;
        int B = 0;
        for (int m = 0; m < NMRG; m++) {
            int nm = g_m1n[row * NMRG + m];
            const int mb = (row * NMRG + m) * MCAP;
            for (int b = 0; b < nm; b++) {
                double cs = g_m1s[mb + b];
                int cc = g_m1c[mb + b];
                while (B > 0 && g_fs[fb + B - 1] * (double)cc < cs * (double)g_fc[fb + B - 1]) {
                    cs += g_fs[fb + B - 1]; cc += g_fc[fb + B - 1]; B--;
                }
                g_fs[fb + B] = cs; g_fc[fb + B] = cc; B++;
            }
        }
        int e = 0;
        for (int b = 0; b < B; b++) {
            e += g_fc[fb + b];
            g_fe[fb + b] = e;
            g_fs[fb + b] = g_fs[fb + b] / (double)g_fc[fb + b];  // -> mean
        }
        g_B[row] = B;
    }
    __syncthreads();

    // Bucket -> block-mean map (one search per nonempty bucket)
    {
        const int fb = row * NBIN;
        const int B = g_B[row];
        #pragma unroll
        for (int j = 0; j < BPT; j++) {
            if (lcnt[j]) {
                int p = (int)lpre[j];
                int loB = 0, hiB = B;
                while (loB < hiB) {
                    int mid = (loB + hiB) >> 1;
                    if (g_fe[fb + mid] > p) hiB = mid; else loB = mid + 1;
                }
                bmean[b0 + j] = (float)g_fs[fb + loB];
            }
        }
    }
}

// ---------------- rank: coalesced map, L2-resident bmean gather --------------
__global__ __launch_bounds__(512) void rank_kernel(
    const float* __restrict__ sims, const float* __restrict__ bmean,
    float* __restrict__ ranks)
{
    const int gi = blockIdx.x * 512 + threadIdx.x;
    if (gi >= TOTAL) return;
    const int row = gi / N;
    float sim = sims[gi];
    unsigned u = __float_as_uint(sim);
    unsigned bin = ((unsigned)row << BINBITS) | (ord_of(u) >> (32 - BINBITS));
    float mean = bmean[bin];
    float z = sim * -10.0f;
    ranks[gi] = (float)((double)z - (double)mean);
}

// ---------------- launch -----------------------------------------------------
extern "C" void kernel_launch(void* const* d_in, const int* in_sizes, int n_in,
                              void* d_out, int out_size)
{
    const float* q = (const float*)d_in[0];
    const float* c = (const float*)d_in[1];
    float* out = (float*)d_out;
    float* sims = out;            // [QN*N]
    float* ranks = out + TOTAL;   // [QN*N]

    void *pc = nullptr, *pz = nullptr, *pm = nullptr;
    cudaGetSymbolAddress(&pc, g_cnt);
    cudaGetSymbolAddress(&pz, g_zsum);
    cudaGetSymbolAddress(&pm, g_bmeanf);

    prep_kernel<<<(QN * NBIN + 511) / 512, 512>>>(q);
    sim_tile_kernel<<<NTB, TILE>>>(c, sims, (unsigned*)pc,
                                   (unsigned long long*)pz);
    pav_bucket_kernel<<<QN, PBT>>>((const unsigned*)pc,
                                   (const unsigned long long*)pz,
                                   (float*)pm);
    rank_kernel<<<(TOTAL + 511) / 512, 512>>>(sims, (const float*)pm, ranks);
}

// round 15
// speedup vs baseline: 1.0925x; 1.0925x over previous
#include <cuda_runtime.h>
#include <cuda_bf16.h>

// Problem constants (fixed shapes)
constexpr int QN = 16;      // query rows
constexpr int D  = 384;     // embedding dim
constexpr int NV = D / 4;   // float4 per row
constexpr int N  = 50000;   // corpus docs
constexpr int TOTAL = QN * N;
constexpr int BINBITS = 13;              // sign+8exp+4mant
constexpr int NBIN = 1 << BINBITS;       // 8192 buckets per row

// GEMM tiling
constexpr int TILE = 128;            // docs per block (1 per thread)
constexpr int KC   = 32;             // k-chunk (floats)
constexpr int NCH  = D / KC;         // 12 chunks
constexpr int NTB  = (N + TILE - 1) / TILE;   // 391 blocks

constexpr int PBT = 1024;            // threads in pav_bucket block
constexpr int BPT = NBIN / PBT;      // 8 bins per thread
constexpr int NMRG = 32;             // level-1 mergers
constexpr int LPM  = PBT / NMRG;     // 32 thread-lists per merger
constexpr int MCAP = LPM * BPT;      // 256 bucket cap (global fallback)
constexpr int SCAP = 3072;           // smem compaction capacity (entries)

constexpr float FXS_F = 4398046511104.0f;  // 2^42 (pow2 -> exact fp32 scale)
constexpr double FXS = 4398046511104.0;

// ---------------- static device scratch (no allocations allowed) ------------
__device__ float              g_qn[QN * D];       // normalized queries
__device__ unsigned           g_cnt[QN * NBIN];   // bucket counts
__device__ unsigned long long g_zsum[QN * NBIN];  // bucket sum(z), fixed-point
__device__ float              g_bmeanf[QN * NBIN];// bucket -> its block mean

// global fallback storage (used only if > SCAP nonempty buckets in a row)
__device__ double g_asum[QN * PBT * BPT];
__device__ int    g_acnt[QN * PBT * BPT];
__device__ int    g_anb[QN * PBT];
__device__ double g_m1s[QN * NMRG * MCAP];
__device__ int    g_m1c[QN * NMRG * MCAP];
__device__ int    g_m1n[QN * NMRG];
__device__ double g_fs[QN * NBIN];
__device__ int    g_fc[QN * NBIN];
__device__ int    g_fe[QN * NBIN];

__device__ __forceinline__ unsigned ord_of(unsigned u) {
    return u ^ ((u & 0x80000000u) ? 0xFFFFFFFFu : 0x80000000u);
}

__device__ __forceinline__ void cp16(void* dst_smem, const void* src) {
    unsigned s = (unsigned)__cvta_generic_to_shared(dst_smem);
    asm volatile("cp.async.cg.shared.global [%0], [%1], 16;" :: "r"(s), "l"(src));
}

__device__ __forceinline__ unsigned long long fma2(
    unsigned long long a, unsigned long long b, unsigned long long c) {
    unsigned long long d;
    asm("fma.rn.f32x2 %0, %1, %2, %3;" : "=l"(d) : "l"(a), "l"(b), "l"(c));
    return d;
}
__device__ __forceinline__ float sum2(unsigned long long v) {
    return __uint_as_float((unsigned)(v & 0xFFFFFFFFull)) +
           __uint_as_float((unsigned)(v >> 32));
}

// ---------------- prep: zero histograms + normalize q ------------------------
__global__ __launch_bounds__(512) void prep_kernel(const float* __restrict__ qg)
{
    const int gid = blockIdx.x * 512 + threadIdx.x;
    if (gid < QN * NBIN) {
        g_cnt[gid] = 0u;
        g_zsum[gid] = 0ull;
    }
    if (blockIdx.x == 0) {
        const int w = threadIdx.x >> 5, lane = threadIdx.x & 31;  // warp = row
        const float4* src = reinterpret_cast<const float4*>(qg) + w * NV;
        float4 v[3];
        float ss = 0.f;
        #pragma unroll
        for (int j = 0; j < 3; j++) {
            v[j] = src[lane + 32 * j];
            ss += v[j].x*v[j].x + v[j].y*v[j].y + v[j].z*v[j].z + v[j].w*v[j].w;
        }
        #pragma unroll
        for (int o = 16; o; o >>= 1)
            ss += __shfl_xor_sync(0xFFFFFFFFu, ss, o);
        float s = 1.0f / fmaxf(sqrtf(ss), 1e-12f);
        float4* dst = reinterpret_cast<float4*>(g_qn) + w * NV;
        #pragma unroll
        for (int j = 0; j < 3; j++) {
            float4 o4 = v[j];
            o4.x *= s; o4.y *= s; o4.z *= s; o4.w *= s;
            dst[lane + 32 * j] = o4;
        }
    }
}

// ---------------- sims GEMM: f32x2 FFMA2, cp.async double-buffered -----------
__global__ __launch_bounds__(TILE) void sim_tile_kernel(
    const float* __restrict__ cg, float* __restrict__ sims,
    unsigned* __restrict__ cnt, unsigned long long* __restrict__ zsum)
{
    __shared__ ulonglong2 qsh[QN * NV];    // 24 KB normalized q
    __shared__ ulonglong2 sc[2][TILE * 8]; // 2 x 16 KB c chunks, XOR-swizzled
    const int tid = threadIdx.x;
    const int d0 = blockIdx.x * TILE;
    const int doc = d0 + tid;
    const bool valid = doc < N;
    const float4* cg4 = reinterpret_cast<const float4*>(cg);

    auto stage = [&](int ch, int buf) {
        const int k4 = ch * (KC / 4);
        #pragma unroll
        for (int i = 0; i < 8; i++) {
            int idx = tid + i * TILE;
            int dd = idx >> 3, f4 = idx & 7;
            int gdoc = min(d0 + dd, N - 1);
            cp16(&sc[buf][dd * 8 + (f4 ^ (dd & 7))],
                 &cg4[(size_t)gdoc * NV + k4 + f4]);
        }
        asm volatile("cp.async.commit_group;" ::: "memory");
    };

    stage(0, 0);
    stage(1, 1);

    {
        const ulonglong2* qn4 = reinterpret_cast<const ulonglong2*>(g_qn);
        #pragma unroll
        for (int i = 0; i < (QN * NV) / TILE; i++)
            qsh[tid + i * TILE] = qn4[tid + i * TILE];
    }

    unsigned long long acc[QN];
    #pragma unroll
    for (int r = 0; r < QN; r++) acc[r] = 0ull;
    unsigned long long ssa = 0ull, ssb = 0ull;

    const int sw = (tid & 7);
    for (int ch = 0; ch < NCH; ch++) {
        if (ch < NCH - 1) asm volatile("cp.async.wait_group 1;" ::: "memory");
        else              asm volatile("cp.async.wait_group 0;" ::: "memory");
        __syncthreads();

        const ulonglong2* crow = &sc[ch & 1][tid * 8];
        const int k4 = ch * (KC / 4);
        #pragma unroll
        for (int f4 = 0; f4 < 8; f4++) {
            ulonglong2 cv = crow[f4 ^ sw];
            ssa = fma2(cv.x, cv.x, ssa);
            ssb = fma2(cv.y, cv.y, ssb);
            #pragma unroll
            for (int r = 0; r < QN; r++) {
                ulonglong2 qv = qsh[r * NV + k4 + f4];
                acc[r] = fma2(qv.x, cv.x, acc[r]);
                acc[r] = fma2(qv.y, cv.y, acc[r]);
            }
        }
        __syncthreads();
        if (ch + 2 < NCH) stage(ch + 2, ch & 1);
    }

    if (valid) {
        float ss = sum2(ssa) + sum2(ssb);
        float cinv = 1.0f / fmaxf(sqrtf(ss), 1e-12f);
        #pragma unroll
        for (int r = 0; r < QN; r++) {
            float sim = sum2(acc[r]) * cinv;
            sims[r * N + doc] = sim;
            unsigned u = __float_as_uint(sim);
            unsigned bin = ((unsigned)r << BINBITS) | (ord_of(u) >> (32 - BINBITS));
            atomicAdd(&cnt[bin], 1u);
            float z = sim * -10.0f;
            long long q = __float2ll_rn(z * FXS_F);
            atomicAdd(&zsum[bin], (unsigned long long)q);
        }
    }
}

// ---------------- fused bucket PAV, smem merge hierarchy ---------------------
// One block per row. Local PAV per thread (8 buckets), compact blocks into
// smem via block scan, 32-way in-place smem PAV merge, final serial merge in
// smem, bucket->mean map from smem. Global fallback if > SCAP entries.
__global__ __launch_bounds__(PBT) void pav_bucket_kernel(
    const unsigned* __restrict__ cnt, const unsigned long long* __restrict__ zsum,
    float* __restrict__ bmean)
{
    __shared__ unsigned s[PBT];
    __shared__ unsigned offarr[PBT];
    __shared__ double csum[SCAP];
    __shared__ int    ccnt[SCAP];
    __shared__ int    mB[NMRG];
    __shared__ int    shB;

    const int row = blockIdx.x;
    const int t = threadIdx.x;
    const int b0 = row * NBIN + t * BPT;

    unsigned lcnt[BPT];
    {
        const uint4* p4 = reinterpret_cast<const uint4*>(cnt + b0);
        #pragma unroll
        for (int j = 0; j < BPT / 4; j++) {
            uint4 v = p4[j];
            lcnt[j*4+0] = v.x; lcnt[j*4+1] = v.y;
            lcnt[j*4+2] = v.z; lcnt[j*4+3] = v.w;
        }
    }
    unsigned tsum = 0;
    #pragma unroll
    for (int j = 0; j < BPT; j++) tsum += lcnt[j];

    // scan 1: element positions
    s[t] = tsum;
    __syncthreads();
    #pragma unroll
    for (int off = 1; off < PBT; off <<= 1) {
        unsigned v = (t >= off) ? s[t - off] : 0u;
        __syncthreads();
        s[t] += v;
        __syncthreads();
    }
    unsigned texcl = s[t] - tsum;

    // local PAV over 8 buckets (registers)
    unsigned lpre[BPT];
    double ls[BPT];
    int    lc[BPT];
    int nb = 0;
    {
        unsigned p = texcl;
        #pragma unroll
        for (int j = 0; j < BPT; j++) {
            lpre[j] = p;
            unsigned c = lcnt[j];
            if (c) {
                double zs = (double)(long long)zsum[b0 + j] * (1.0 / FXS);
                double dc = (double)c;
                double cs = zs - dc * (double)N + dc * (double)p
                            + 0.5 * dc * (double)(c - 1);
                int cc = (int)c;
                while (nb > 0 && ls[nb - 1] * (double)cc < cs * (double)lc[nb - 1]) {
                    cs += ls[nb - 1]; cc += lc[nb - 1]; nb--;
                }
                ls[nb] = cs; lc[nb] = cc; nb++;
            }
            p += c;
        }
    }

    // scan 2: compaction offsets
    __syncthreads();
    s[t] = (unsigned)nb;
    __syncthreads();
    #pragma unroll
    for (int off = 1; off < PBT; off <<= 1) {
        unsigned v = (t >= off) ? s[t - off] : 0u;
        __syncthreads();
        s[t] += v;
        __syncthreads();
    }
    const unsigned myoff = s[t] - (unsigned)nb;
    offarr[t] = myoff;
    __syncthreads();
    const unsigned T = s[PBT - 1];

    if (T <= (unsigned)SCAP) {
        // ---------- smem path ----------
        for (int b = 0; b < nb; b++) {
            csum[myoff + b] = ls[b];
            ccnt[myoff + b] = lc[b];
        }
        __syncthreads();

        if (t < NMRG) {
            const int beg = (int)offarr[t * LPM];
            const int end = (t == NMRG - 1) ? (int)T : (int)offarr[(t + 1) * LPM];
            int B = 0;   // stack in place at [beg, beg+B)
            for (int i = beg; i < end; i++) {
                double cs = csum[i]; int cc = ccnt[i];
                while (B > 0 && csum[beg + B - 1] * (double)cc < cs * (double)ccnt[beg + B - 1]) {
                    cs += csum[beg + B - 1]; cc += ccnt[beg + B - 1]; B--;
                }
                csum[beg + B] = cs; ccnt[beg + B] = cc; B++;
            }
            mB[t] = B;
        }
        __syncthreads();

        if (t == 0) {
            int B = 0;   // final stack compacted from index 0 (write idx <= read idx)
            for (int m = 0; m < NMRG; m++) {
                const int beg = (int)offarr[m * LPM];
                const int bm = mB[m];
                for (int b = 0; b < bm; b++) {
                    double cs = csum[beg + b]; int cc = ccnt[beg + b];
                    while (B > 0 && csum[B - 1] * (double)cc < cs * (double)ccnt[B - 1]) {
                        cs += csum[B - 1]; cc += ccnt[B - 1]; B--;
                    }
                    csum[B] = cs; ccnt[B] = cc; B++;
                }
            }
            int e = 0;
            for (int b = 0; b < B; b++) {
                csum[b] = csum[b] / (double)ccnt[b];  // -> mean
                e += ccnt[b];
                ccnt[b] = e;                           // -> end position
            }
            shB = B;
        }
        __syncthreads();

        const int B = shB;
        #pragma unroll
        for (int j = 0; j < BPT; j++) {
            if (lcnt[j]) {
                int p = (int)lpre[j];
                int loB = 0, hiB = B;
                while (loB < hiB) {
                    int mid = (loB + hiB) >> 1;
                    if (ccnt[mid] > p) hiB = mid; else loB = mid + 1;
                }
                bmean[b0 + j] = (float)csum[loB];
            }
        }
    } else {
        // ---------- global fallback (rare: > SCAP nonempty buckets) ----------
        const int ob = (row * PBT + t) * BPT;
        for (int b = 0; b < nb; b++) {
            g_asum[ob + b] = ls[b];
            g_acnt[ob + b] = lc[b];
        }
        g_anb[row * PBT + t] = nb;
        __syncthreads();

        if (t < NMRG) {
            const int mb = (row * NMRG + t) * MCAP;
            int B = 0;
            for (int tt = t * LPM; tt < t * LPM + LPM; tt++) {
                int nbt = g_anb[row * PBT + tt];
                const int bb = (row * PBT + tt) * BPT;
                for (int b = 0; b < nbt; b++) {
                    double cs = g_asum[bb + b];
                    int cc = g_acnt[bb + b];
                    while (B > 0 && g_m1s[mb + B - 1] * (double)cc < cs * (double)g_m1c[mb + B - 1]) {
                        cs += g_m1s[mb + B - 1]; cc += g_m1c[mb + B - 1]; B--;
                    }
                    g_m1s[mb + B] = cs; g_m1c[mb + B] = cc; B++;
                }
            }
            g_m1n[row * NMRG + t] = B;
        }
        __syncthreads();

        if (t == 0) {
            const int fb = row * NBIN;
            int B = 0;
            for (int m = 0; m < NMRG; m++) {
                int nm = g_m1n[row * NMRG + m];
                const int mb = (row * NMRG + m) * MCAP;
                for (int b = 0; b < nm; b++) {
                    double cs = g_m1s[mb + b];
                    int cc = g_m1c[mb + b];
                    while (B > 0 && g_fs[fb + B - 1] * (double)cc < cs * (double)g_fc[fb + B - 1]) {
                        cs += g_fs[fb + B - 1]; cc += g_fc[fb + B - 1]; B--;
                    }
                    g_fs[fb + B] = cs; g_fc[fb + B] = cc; B++;
                }
            }
            int e = 0;
            for (int b = 0; b < B; b++) {
                e += g_fc[fb + b];
                g_fe[fb + b] = e;
                g_fs[fb + b] = g_fs[fb + b] / (double)g_fc[fb + b];
            }
            shB = B;
        }
        __syncthreads();

        const int fb = row * NBIN;
        const int B = shB;
        #pragma unroll
        for (int j = 0; j < BPT; j++) {
            if (lcnt[j]) {
                int p = (int)lpre[j];
                int loB = 0, hiB = B;
                while (loB < hiB) {
                    int mid = (loB + hiB) >> 1;
                    if (g_fe[fb + mid] > p) hiB = mid; else loB = mid + 1;
                }
                bmean[b0 + j] = (float)g_fs[fb + loB];
            }
        }
    }
}

// ---------------- rank: 4-wide coalesced map, L2 bmean gather ----------------
// N % 4 == 0, so an aligned float4 never straddles a row boundary.
__global__ __launch_bounds__(256) void rank_kernel(
    const float* __restrict__ sims, const float* __restrict__ bmean,
    float* __restrict__ ranks)
{
    const int i4 = blockIdx.x * 256 + threadIdx.x;
    const int gi = i4 * 4;
    if (gi >= TOTAL) return;
    const int row = gi / N;
    const unsigned rbase = (unsigned)row << BINBITS;

    float4 sv = reinterpret_cast<const float4*>(sims)[i4];
    float sm[4] = {sv.x, sv.y, sv.z, sv.w};
    float mn[4];
    #pragma unroll
    for (int j = 0; j < 4; j++) {
        unsigned u = __float_as_uint(sm[j]);
        mn[j] = bmean[rbase | (ord_of(u) >> (32 - BINBITS))];
    }
    float4 out;
    out.x = (float)((double)(sm[0] * -10.0f) - (double)mn[0]);
    out.y = (float)((double)(sm[1] * -10.0f) - (double)mn[1]);
    out.z = (float)((double)(sm[2] * -10.0f) - (double)mn[2]);
    out.w = (float)((double)(sm[3] * -10.0f) - (double)mn[3]);
    reinterpret_cast<float4*>(ranks)[i4] = out;
}

// ---------------- launch -----------------------------------------------------
extern "C" void kernel_launch(void* const* d_in, const int* in_sizes, int n_in,
                              void* d_out, int out_size)
{
    const float* q = (const float*)d_in[0];
    const float* c = (const float*)d_in[1];
    float* out = (float*)d_out;
    float* sims = out;            // [QN*N]
    float* ranks = out + TOTAL;   // [QN*N]

    void *pc = nullptr, *pz = nullptr, *pm = nullptr;
    cudaGetSymbolAddress(&pc, g_cnt);
    cudaGetSymbolAddress(&pz, g_zsum);
    cudaGetSymbolAddress(&pm, g_bmeanf);

    prep_kernel<<<(QN * NBIN + 511) / 512, 512>>>(q);
    sim_tile_kernel<<<NTB, TILE>>>(c, sims, (unsigned*)pc,
                                   (unsigned long long*)pz);
    pav_bucket_kernel<<<QN, PBT>>>((const unsigned*)pc,
                                   (const unsigned long long*)pz,
                                   (float*)pm);
    rank_kernel<<<(TOTAL / 4 + 255) / 256, 256>>>(sims, (const float*)pm, ranks);
}